// round 9
// baseline (speedup 1.0000x reference)
#include <cuda_runtime.h>

// Problem constants (shapes fixed by the dataset)
#define B 16
#define F 256
#define T 8192
#define KKEEP 204                 // k = int(256 * (1 - 0.2))

#define N1 (B * F * T)            // 33,554,432 floats per output tensor
#define N4_MASKED (N1 / 4)        // 8,388,608 float4 (masked_x half)

// Streamer geometry (R8-proven): 256 threads, ILP 4 -> 1024 f4 per block.
#define BLK_F4 1024
#define MASKED_BLOCKS 8192        // 8192 * 1024 f4 = N4_MASKED
#define BCAST_BLOCKS 8192
#define GRID_TOTAL (MASKED_BLOCKS + BCAST_BLOCKS)

// Per-(b,f) binary mask + handshake counters (reset at end of every launch).
__device__ __align__(16) float g_mask[B * F];
__device__ int g_done;            // mask rows completed this launch (0..16)
__device__ int g_exit;            // blocks retired this launch

// kept(f) <=> #{j : x2[j] > x2[f]} < KKEEP   (tie-correct vs top_k kth value)
// binary  = kept && (x2 > 0)                 (probs > 0.5 <=> wta > 0)
__global__ void fused_kernel(const float* __restrict__ w_mask,
                             const float* __restrict__ noise,
                             const float4* __restrict__ x,
                             float4* __restrict__ out) {
    const int tid = threadIdx.x;                      // 256 threads
    const int bid = blockIdx.x;

    // ---- Phase 1: blocks 0..15 produce the mask row for batch == bid ----
    if (bid < B) {
        __shared__ float s[F];
        const float w  = w_mask[tid];
        const float sg = 1.0f / (1.0f + __expf(-w));
        const float x2 = sg + 0.05f * noise[bid * F + tid];
        s[tid] = x2;
        __syncthreads();
        int gt = 0;
#pragma unroll 16
        for (int j = 0; j < F; ++j)
            gt += (s[j] > x2) ? 1 : 0;                // uniform-addr LDS: N=1
        g_mask[bid * F + tid] = (gt < KKEEP && x2 > 0.0f) ? 1.0f : 0.0f;
        __threadfence();                              // row visible at L2
        __syncthreads();                              // all 256 lanes fenced
        if (tid == 0) atomicAdd(&g_done, 1);          // release
    }

    // ---- Phase 2: acquire — wait until all 16 mask rows are published ----
    if (tid == 0) {
        int ns = 32;
        while (*((volatile int*)&g_done) < B) {       // acquire poll
            __nanosleep(ns);
            if (ns < 1024) ns <<= 1;                  // backoff: cap poll rate
        }
    }
    __syncthreads();

    // ---- Phase 3: R8 streamer body (unchanged, zero further barriers) ----
    if (bid < MASKED_BLOCKS) {
        const int baseV = bid * BLK_F4;               // first f4 index
        const int row   = baseV >> 11;                // (b*F + f), uniform
        const float m   = __ldg(&g_mask[row]);        // post-acquire, L2-valid

        if (m != 0.0f) {
            float4 xv[4];
#pragma unroll
            for (int k = 0; k < 4; ++k)               // front-batched (MLP=4)
                xv[k] = __ldcs(&x[baseV + k * 256 + tid]);
#pragma unroll
            for (int k = 0; k < 4; ++k)
                __stcs(&out[baseV + k * 256 + tid], xv[k]);
        } else {
            const float4 z = make_float4(0.f, 0.f, 0.f, 0.f);
#pragma unroll
            for (int k = 0; k < 4; ++k)               // row dropped: no reads
                __stcs(&out[baseV + k * 256 + tid], z);
        }
    } else {
        const int w0 = (bid - MASKED_BLOCKS) * BLK_F4;
        const int b  = w0 >> 19;                      // T*F/4 f4 per batch
        const int baseV = N4_MASKED + w0;
        // f4 lane = (w0 + k*256 + tid) & 63 = tid & 63 (w0, 256 ≡ 0 mod 64)
        const float4 m4 =
            __ldg(&((const float4*)g_mask)[(b << 6) + (tid & 63)]);
#pragma unroll
        for (int k = 0; k < 4; ++k)
            __stcs(&out[baseV + k * 256 + tid], m4);
    }

    // ---- Phase 4: last block out resets counters -> next launch is clean ---
    if (tid == 0) {
        const int n = atomicAdd(&g_exit, 1);
        if (n == (int)gridDim.x - 1) {                // everyone passed spin
            g_exit = 0;
            g_done = 0;
        }
    }
}

extern "C" void kernel_launch(void* const* d_in, const int* in_sizes, int n_in,
                              void* d_out, int out_size) {
    const float* x      = (const float*)d_in[0];   // (16,1,256,8192) f32
    const float* w_mask = (const float*)d_in[1];   // (1,1,1,256)     f32
    const float* noise  = (const float*)d_in[2];   // (16,1,1,256)    f32
    float* out = (float*)d_out;

    const bool has_bcast = ((long long)out_size >= 2LL * N1);
    const int blocks = has_bcast ? GRID_TOTAL : MASKED_BLOCKS;
    fused_kernel<<<blocks, 256>>>(w_mask, noise,
                                  (const float4*)x, (float4*)out);
}

// round 10
// speedup vs baseline: 1.0112x; 1.0112x over previous
#include <cuda_runtime.h>

// Problem constants (shapes fixed by the dataset)
#define B 16
#define F 256
#define T 8192
#define KKEEP 204                 // k = int(256 * (1 - 0.2))

#define N1 (B * F * T)            // 33,554,432 floats per output tensor
#define N4_MASKED (N1 / 4)        // 8,388,608 float4 (masked_x half)

// Streamer geometry (R8-proven): 256 threads, ILP 4 -> 1024 f4 per block.
#define BLK_F4 1024
#define MASKED_BLOCKS 8192        // 8192 * 1024 f4 = N4_MASKED
#define BCAST_BLOCKS 8192
#define GRID_TOTAL (MASKED_BLOCKS + BCAST_BLOCKS)

// Per-(b,f) binary mask, produced by K1, consumed by K2 after grid-dep sync.
__device__ __align__(16) float g_mask[B * F];

// ---------------------------------------------------------------------------
// K1: binary[b,f].  grid=16, block=256.
// kept(f) <=> #{j : x2[j] > x2[f]} < KKEEP   (tie-correct vs top_k kth value)
// binary  = kept && (x2 > 0)                 (probs > 0.5 <=> wta > 0)
// Triggers programmatic launch completion once its row is written + fenced.
// ---------------------------------------------------------------------------
__global__ void mask_kernel(const float* __restrict__ w_mask,
                            const float* __restrict__ noise) {
    __shared__ float s[F];
    const int b = blockIdx.x;
    const int f = threadIdx.x;

    const float w  = w_mask[f];
    const float sg = 1.0f / (1.0f + __expf(-w));
    const float x2 = sg + 0.05f * noise[b * F + f];
    s[f] = x2;
    __syncthreads();

    int gt = 0;
#pragma unroll 16
    for (int j = 0; j < F; ++j)
        gt += (s[j] > x2) ? 1 : 0;                    // uniform-addr LDS: N=1
    g_mask[b * F + f] = (gt < KKEEP && x2 > 0.0f) ? 1.0f : 0.0f;
    __threadfence();                                  // publish before trigger
    __syncthreads();
    cudaTriggerProgrammaticLaunchCompletion();        // let K2 ramp up now
}

// ---------------------------------------------------------------------------
// K2: merged streamer (R8 body), zero barriers + read-skip.
// Launched with ProgrammaticStreamSerialization: blocks may start during K1's
// tail; cudaGridDependencySynchronize() enforces mask visibility.
// ---------------------------------------------------------------------------
__global__ void stream_kernel(const float4* __restrict__ x,
                              float4* __restrict__ out) {
    cudaGridDependencySynchronize();                  // wait for K1's writes

    const int tid = threadIdx.x;                      // 256 threads

    if (blockIdx.x < MASKED_BLOCKS) {
        const int baseV = blockIdx.x * BLK_F4;        // first f4 index
        const int row   = baseV >> 11;                // (b*F + f), uniform
        const float m   = __ldg(&g_mask[row]);        // L1/L2 broadcast

        if (m != 0.0f) {
            float4 xv[4];
#pragma unroll
            for (int k = 0; k < 4; ++k)               // front-batched (MLP=4)
                xv[k] = __ldcs(&x[baseV + k * 256 + tid]);
#pragma unroll
            for (int k = 0; k < 4; ++k)
                __stcs(&out[baseV + k * 256 + tid], xv[k]);
        } else {
            const float4 z = make_float4(0.f, 0.f, 0.f, 0.f);
#pragma unroll
            for (int k = 0; k < 4; ++k)               // row dropped: no reads
                __stcs(&out[baseV + k * 256 + tid], z);
        }
    } else {
        const int w0 = (blockIdx.x - MASKED_BLOCKS) * BLK_F4;
        const int b  = w0 >> 19;                      // T*F/4 f4 per batch
        const int baseV = N4_MASKED + w0;
        // f4 lane = (w0 + k*256 + tid) & 63 = tid & 63 (w0, 256 ≡ 0 mod 64)
        const float4 m4 =
            __ldg(&((const float4*)g_mask)[(b << 6) + (tid & 63)]);
#pragma unroll
        for (int k = 0; k < 4; ++k)
            __stcs(&out[baseV + k * 256 + tid], m4);
    }
}

extern "C" void kernel_launch(void* const* d_in, const int* in_sizes, int n_in,
                              void* d_out, int out_size) {
    const float* x      = (const float*)d_in[0];   // (16,1,256,8192) f32
    const float* w_mask = (const float*)d_in[1];   // (1,1,1,256)     f32
    const float* noise  = (const float*)d_in[2];   // (16,1,1,256)    f32
    float* out = (float*)d_out;

    // K1: normal launch on the capture (legacy default) stream.
    mask_kernel<<<B, F>>>(w_mask, noise);

    // K2: PDL launch — overlaps its ramp with K1's tail.
    const bool has_bcast = ((long long)out_size >= 2LL * N1);
    const int blocks = has_bcast ? GRID_TOTAL : MASKED_BLOCKS;

    cudaLaunchConfig_t cfg = {};
    cfg.gridDim  = dim3((unsigned)blocks, 1, 1);
    cfg.blockDim = dim3(256, 1, 1);
    cfg.dynamicSmemBytes = 0;
    cfg.stream = 0;                                   // same (capture) stream

    cudaLaunchAttribute attr[1];
    attr[0].id = cudaLaunchAttributeProgrammaticStreamSerialization;
    attr[0].val.programmaticStreamSerializationAllowed = 1;
    cfg.attrs = attr;
    cfg.numAttrs = 1;

    cudaLaunchKernelEx(&cfg, stream_kernel, (const float4*)x, (float4*)out);
}